// round 15
// baseline (speedup 1.0000x reference)
#include <cuda_runtime.h>
#include <stdint.h>

// Problem constants
#define BB 16
#define CC 4
#define HH 512
#define WW 1024
#define ROWS (BB * CC * HH)       // 32768
#define NBLK (ROWS / 8)           // 4096 streaming blocks, 8 rows each
#define BCN  (BB * CC)            // 64 (b,c) groups; 64 blocks per group

// Per-block partials (err_sum, cnt_sum). cnt_sum >= 0 once written;
// sentinel cnt_sum = -1 means "not yet written". Re-initialized by the
// (first, ~free) init node on every launch/replay.
__device__ float2 g_part[NBLK];

// ---------------------------------------------------------------------------
// Kernel A (init, first node ~free): set all partials to the sentinel.
// ---------------------------------------------------------------------------
__global__ __launch_bounds__(256) void init_kernel()
{
    const int i = blockIdx.x * 256 + threadIdx.x;   // 16 x 256 = 4096
    g_part[i] = make_float2(0.0f, -1.0f);
}

// ---------------------------------------------------------------------------
// Kernel B: NBLK streaming blocks + 1 finisher block, one grid.
//
// Streaming blocks (0..NBLK-1): exact proven 22.1us body — one warp per row,
//   front-batched .cs loads, serial first-max argmax, one __syncthreads,
//   8-row smem reduce, ONE plain STG.cg of the float2 partial. No atomics.
//
// Finisher block (NBLK): scheduled in the last wave. 256 threads poll their
//   16 slots each (ld.cg; ready when cnt >= 0), accumulate in fixed order,
//   compute per-(b,c) means, and write the scalar. Deterministic.
// ---------------------------------------------------------------------------
__global__ __launch_bounds__(256) void offset_loss_kernel(
    const float* __restrict__ offset_pred,
    const float* __restrict__ offset_true,
    const float* __restrict__ cls_true,
    const float* __restrict__ vertical_true,
    float* __restrict__ out)
{
    if (blockIdx.x == NBLK) {
        // ---------------- Finisher block ----------------
        const int t = threadIdx.x;          // 0..255; 4 threads per bc group

        float esum = 0.0f;
        float csum = 0.0f;
        // Thread t owns 16 consecutive slots, all inside bc = t >> 2.
#pragma unroll 1
        for (int j = 0; j < 16; j++) {
            const int slot = t * 16 + j;
            float2 p;
            for (;;) {
                p = __ldcg(&g_part[slot]);  // L2 load, bypasses L1
                if (p.y >= 0.0f) break;     // written (cnt_sum >= 0)
                __nanosleep(256);
            }
            esum += p.x;
            csum += p.y;
        }

        // Reduce the 4 threads of each bc group (lanes 4k..4k+3, aligned).
#pragma unroll
        for (int off = 1; off < 4; off <<= 1) {
            esum += __shfl_xor_sync(0xffffffffu, esum, off);
            csum += __shfl_xor_sync(0xffffffffu, csum, off);
        }

        __shared__ float s_pbc[BCN];
        if ((t & 3) == 0) {
            s_pbc[t >> 2] = (csum > 0.0f) ? (esum / fmaxf(csum, 1.0f)) : 0.0f;
        }
        __syncthreads();

        if (t < 32) {
            float vsum = s_pbc[t] + s_pbc[t + 32];
#pragma unroll
            for (int off = 16; off > 0; off >>= 1) {
                vsum += __shfl_xor_sync(0xffffffffu, vsum, off);
            }
            if (t == 0) out[0] = vsum / (float)BB;
        }
        return;
    }

    // ---------------- Streaming blocks (proven body) ----------------
    const int warp_in_block = threadIdx.x >> 5;
    const int lane = threadIdx.x & 31;
    const int row = blockIdx.x * 8 + warp_in_block;

    const float4* crow = reinterpret_cast<const float4*>(cls_true + (size_t)row * WW);

    // Front-batch all 8 coalesced float4 loads (512B/warp each) -> MLP 8.
    float4 v[8];
#pragma unroll
    for (int k = 0; k < 8; k++) {
        v[k] = __ldcs(&crow[k * 32 + lane]);   // streaming: read-once data
    }

    // Per-lane scan in increasing index order (first-max within lane).
    float best = -__int_as_float(0x7f800000);  // -inf
    int   bidx = 0;
#pragma unroll
    for (int k = 0; k < 8; k++) {
        const int base = (k * 32 + lane) * 4;
        if (v[k].x > best) { best = v[k].x; bidx = base + 0; }
        if (v[k].y > best) { best = v[k].y; bidx = base + 1; }
        if (v[k].z > best) { best = v[k].z; bidx = base + 2; }
        if (v[k].w > best) { best = v[k].w; bidx = base + 3; }
    }

    // Warp reduction: larger value wins; exact tie -> smaller index (first-max).
#pragma unroll
    for (int off = 16; off > 0; off >>= 1) {
        float oval = __shfl_xor_sync(0xffffffffu, best, off);
        int   oidx = __shfl_xor_sync(0xffffffffu, bidx, off);
        if (oval > best || (oval == best && oidx < bidx)) {
            best = oval;
            bidx = oidx;
        }
    }

    // Lane 0 of each warp: gather + mask for this row.
    __shared__ float s_err[8];
    __shared__ float s_cnt[8];
    if (lane == 0) {
        const size_t gidx = (size_t)row * WW + bidx;
        float p = __ldg(&offset_pred[gidx]);
        float t = __ldg(&offset_true[gidx]);
        float mask = (__ldg(&vertical_true[row]) >= 0.5f) ? 1.0f : 0.0f;
        s_err[warp_in_block] = fabsf(p - t) * mask;
        s_cnt[warp_in_block] = mask;
    }
    __syncthreads();

    // Warp 0, lanes 0..7 reduce the 8 row results; thread 0 stores the
    // partial with ONE plain STG.cg (no atomics, no fences).
    if (threadIdx.x < 8) {
        float e = s_err[threadIdx.x];
        float c = s_cnt[threadIdx.x];
#pragma unroll
        for (int off = 4; off > 0; off >>= 1) {
            e += __shfl_xor_sync(0x000000ffu, e, off);
            c += __shfl_xor_sync(0x000000ffu, c, off);
        }
        if (threadIdx.x == 0) {
            __stcg(&g_part[blockIdx.x], make_float2(e, c));
        }
    }
}

// ---------------------------------------------------------------------------
extern "C" void kernel_launch(void* const* d_in, const int* in_sizes, int n_in,
                              void* d_out, int out_size)
{
    const float* offset_pred   = (const float*)d_in[0];
    const float* offset_true   = (const float*)d_in[1];
    const float* cls_true      = (const float*)d_in[2];
    const float* vertical_true = (const float*)d_in[3];
    float* out = (float*)d_out;

    // First node (~free): reset sentinels for this replay.
    init_kernel<<<NBLK / 256, 256>>>();

    // One grid: 4096 streaming blocks + 1 polling finisher block.
    offset_loss_kernel<<<NBLK + 1, 256>>>(offset_pred, offset_true, cls_true,
                                          vertical_true, out);
}

// round 16
// speedup vs baseline: 1.1440x; 1.1440x over previous
#include <cuda_runtime.h>
#include <stdint.h>

// Problem constants
#define BB 16
#define CC 4
#define HH 512
#define WW 1024
#define ROWS (BB * CC * HH)       // 32768
#define NBLK (ROWS / 8)           // 4096 blocks, 8 rows each
#define BCN  (BB * CC)            // 64 (b,c) groups; 64 blocks per group

// Per-(b,c) accumulators, padded to 128B stride (per-CTA-distinct lines —
// spread REDs are fast; single-address RMW is the proven poison).
// Zero-initialized at module load; the finisher resets them after reading.
__device__ float g_acc[BCN][32];

// ---------------------------------------------------------------------------
// Kernel 1 (streaming, R7-proven body + early PDL trigger): one warp per row,
// 8 rows per block. Argmax over W=1024 (first-max), gather offsets, mask,
// smem-reduce 8 rows, two fire-and-forget REDG.ADDs to the block's (b,c)
// line. The launch_dependents at entry lets the finisher node launch when
// the LAST WAVE STARTS, hiding its ~3us launch overhead behind the stream.
// ---------------------------------------------------------------------------
__global__ __launch_bounds__(256) void row_argmax_kernel(
    const float* __restrict__ offset_pred,
    const float* __restrict__ offset_true,
    const float* __restrict__ cls_true,
    const float* __restrict__ vertical_true)
{
    if (threadIdx.x == 0) {
        asm volatile("griddepcontrol.launch_dependents;");
    }

    const int warp_in_block = threadIdx.x >> 5;
    const int lane = threadIdx.x & 31;
    const int row = blockIdx.x * 8 + warp_in_block;

    const float4* crow = reinterpret_cast<const float4*>(cls_true + (size_t)row * WW);

    // Front-batch all 8 coalesced float4 loads (512B/warp each) -> MLP 8.
    float4 v[8];
#pragma unroll
    for (int k = 0; k < 8; k++) {
        v[k] = __ldcs(&crow[k * 32 + lane]);   // streaming: read-once data
    }

    // Per-lane scan in increasing index order (first-max within lane).
    float best = -__int_as_float(0x7f800000);  // -inf
    int   bidx = 0;
#pragma unroll
    for (int k = 0; k < 8; k++) {
        const int base = (k * 32 + lane) * 4;
        if (v[k].x > best) { best = v[k].x; bidx = base + 0; }
        if (v[k].y > best) { best = v[k].y; bidx = base + 1; }
        if (v[k].z > best) { best = v[k].z; bidx = base + 2; }
        if (v[k].w > best) { best = v[k].w; bidx = base + 3; }
    }

    // Warp reduction: larger value wins; exact tie -> smaller index (first-max).
#pragma unroll
    for (int off = 16; off > 0; off >>= 1) {
        float oval = __shfl_xor_sync(0xffffffffu, best, off);
        int   oidx = __shfl_xor_sync(0xffffffffu, bidx, off);
        if (oval > best || (oval == best && oidx < bidx)) {
            best = oval;
            bidx = oidx;
        }
    }

    // Lane 0 of each warp: gather + mask for this row.
    __shared__ float s_err[8];
    __shared__ float s_cnt[8];
    if (lane == 0) {
        const size_t gidx = (size_t)row * WW + bidx;
        float p = __ldg(&offset_pred[gidx]);
        float t = __ldg(&offset_true[gidx]);
        float mask = (__ldg(&vertical_true[row]) >= 0.5f) ? 1.0f : 0.0f;
        s_err[warp_in_block] = fabsf(p - t) * mask;
        s_cnt[warp_in_block] = mask;
    }
    __syncthreads();

    // Warp 0, lanes 0..7 reduce the 8 row results; thread 0 fires two REDs
    // to this block's (b,c)-distinct 128B line (no return value, no wait).
    if (threadIdx.x < 8) {
        float e = s_err[threadIdx.x];
        float c = s_cnt[threadIdx.x];
#pragma unroll
        for (int off = 4; off > 0; off >>= 1) {
            e += __shfl_xor_sync(0x000000ffu, e, off);
            c += __shfl_xor_sync(0x000000ffu, c, off);
        }
        if (threadIdx.x == 0) {
            const int bc = blockIdx.x >> 6;     // 64 blocks per group
            atomicAdd(&g_acc[bc][0], e);        // REDG.ADD (result unused)
            atomicAdd(&g_acc[bc][1], c);
        }
    }
}

// ---------------------------------------------------------------------------
// Kernel 2 (finisher, PDL secondary): launches when the primary's last wave
// begins (launch_dependents fired per-block at entry); the device-side
// gridDependencySynchronize is a HW wait for full primary completion — no
// polling loads, no stream interference. Then: read the 64 L2-hot pairs,
// per-group means, reduce, write scalar, reset accumulators for replay.
// ---------------------------------------------------------------------------
__global__ __launch_bounds__(64) void final_reduce_kernel(float* __restrict__ out)
{
#if __CUDA_ARCH__ >= 900
    cudaGridDependencySynchronize();
#endif

    const int t = threadIdx.x;   // 0..63

    float e = g_acc[t][0];
    float c = g_acc[t][1];
    float pbc = (c > 0.0f) ? (e / fmaxf(c, 1.0f)) : 0.0f;

    // Reset for the next replay (visible at kernel boundary).
    g_acc[t][0] = 0.0f;
    g_acc[t][1] = 0.0f;

    // Reduce 64 values across 2 warps.
    __shared__ float s_w[2];
#pragma unroll
    for (int off = 16; off > 0; off >>= 1) {
        pbc += __shfl_xor_sync(0xffffffffu, pbc, off);
    }
    if ((t & 31) == 0) s_w[t >> 5] = pbc;
    __syncthreads();

    if (t == 0) {
        out[0] = (s_w[0] + s_w[1]) / (float)BB;
    }
}

// ---------------------------------------------------------------------------
extern "C" void kernel_launch(void* const* d_in, const int* in_sizes, int n_in,
                              void* d_out, int out_size)
{
    const float* offset_pred   = (const float*)d_in[0];
    const float* offset_true   = (const float*)d_in[1];
    const float* cls_true      = (const float*)d_in[2];
    const float* vertical_true = (const float*)d_in[3];
    float* out = (float*)d_out;

    row_argmax_kernel<<<NBLK, 256>>>(offset_pred, offset_true, cls_true,
                                     vertical_true);

    // PDL finisher: may launch once every primary block has fired
    // launch_dependents (start of the primary's last wave).
    cudaLaunchAttribute attrs[1];
    attrs[0].id = cudaLaunchAttributeProgrammaticStreamSerialization;
    attrs[0].val.programmaticStreamSerializationAllowed = 1;

    cudaLaunchConfig_t cfg = {};
    cfg.gridDim = dim3(1, 1, 1);
    cfg.blockDim = dim3(64, 1, 1);
    cfg.dynamicSmemBytes = 0;
    cfg.stream = 0;
    cfg.attrs = attrs;
    cfg.numAttrs = 1;

    cudaLaunchKernelEx(&cfg, final_reduce_kernel, out);
}